// round 7
// baseline (speedup 1.0000x reference)
#include <cuda_runtime.h>
#include <cuda_fp16.h>
#include <math.h>

// ---------------- problem constants ----------------
#define NN   100000
#define EE0  1600000            // raw edges
#define EETOT (EE0 + NN)        // + self loops
#define C1   64                 // in channels
#define H1   4                  // heads layer1
#define HC1  128                // H1*D1
#define OUTC 32                 // layer2 out channels
#define NB_SCAN 98              // ceil(NN/1024)

typedef unsigned long long u64;
#define FMA_X2(d, a, b, c) \
    asm("fma.rn.f32x2 %0, %1, %2, %3;" : "=l"(d) : "l"(a), "l"(b), "l"(c))
#define PACK2(d, lo, hi) \
    asm("mov.b64 %0, {%1, %2};" : "=l"(d) : "f"(lo), "f"(hi))
#define UNPACK2(lo, hi, s) \
    asm("mov.b64 {%0, %1}, %2;" : "=f"(lo), "=f"(hi) : "l"(s))

union F4U2 { float4 f4; u64 u[2]; };

// ---------------- scratch (device globals; no allocation) ----------------
__device__ __half g_h1h[NN * HC1];      // layer1 features (fp16, gather-only)
__device__ __half g_out1h[NN * HC1];    // elu(agg1 + b1) (fp16, gemm2 input)
__device__ float  g_al_src1[NN * H1];
__device__ float  g_al_dst1[NN * H1];

__device__ __half g_h2h[NN * OUTC];     // layer2 features (fp16, gather-only)
__device__ float  g_al_src2[NN];
__device__ float  g_al_dst2[NN];

// CSR build: g_degx = [deg[NN], ticket, flag]  (zeroed by one memset node)
__device__ int g_degx[NN + 2];
__device__ int g_cursor[NN];
__device__ int g_bsum[NB_SCAN];
__device__ int g_boff[NB_SCAN];
__device__ int g_off[NN + 1];
__device__ int g_esrc[EETOT];

// ---------------- helpers ----------------
__device__ __forceinline__ float leaky(float v) { return v > 0.f ? v : 0.2f * v; }

// int64 little-endian edges => int32 view has zero high words (indices < 2^31)
__device__ __forceinline__ int detect_is64(const int* __restrict__ ei) {
    int zeros = 0;
#pragma unroll
    for (int k = 0; k < 16; k++) zeros += (ei[2 * k + 1] == 0);
    return zeros == 16;
}

__device__ __forceinline__ void h4load(const __half* p, float& f0, float& f1,
                                       float& f2, float& f3) {
    uint2 u = *reinterpret_cast<const uint2*>(p);
    __half2 a = *reinterpret_cast<__half2*>(&u.x);
    __half2 b = *reinterpret_cast<__half2*>(&u.y);
    float2 fa = __half22float2(a), fb = __half22float2(b);
    f0 = fa.x; f1 = fa.y; f2 = fb.x; f3 = fb.y;
}

// ---------------- GEMM1 + fused logits1 + fused dst histogram ----------------
// h1[N,128] = x[N,64] @ W1[64,128]; al_src1/al_dst1[N,4]; g_deg histogram
#define G1_ROWS 64
__global__ __launch_bounds__(256) void gemm1_kernel(const float* __restrict__ x,
                                                    const float* __restrict__ W,
                                                    const float* __restrict__ asrc,
                                                    const float* __restrict__ adst,
                                                    const int* __restrict__ ei) {
    __shared__ float xst[C1][G1_ROWS];   // [k][row] 16 KB
    __shared__ float Ws[C1][HC1];        // 32 KB
    __shared__ int sh_is64;
    int tid = threadIdx.x;
    int row0 = blockIdx.x * G1_ROWS;
    if (tid == 0) sh_is64 = detect_is64(ei);

    const float4* W4 = (const float4*)W;
    float4* Ws4 = (float4*)Ws;
#pragma unroll
    for (int i = 0; i < 8; i++) Ws4[tid + 256 * i] = W4[tid + 256 * i];
#pragma unroll
    for (int i = 0; i < 4; i++) {
        int idx = tid + 256 * i;          // float4 idx; 16 per row
        int r = idx >> 4, k4 = idx & 15;
        int row = row0 + r;
        float4 v = make_float4(0.f, 0.f, 0.f, 0.f);
        if (row < NN) v = *(const float4*)&x[row * C1 + k4 * 4];
        xst[k4 * 4 + 0][r] = v.x; xst[k4 * 4 + 1][r] = v.y;
        xst[k4 * 4 + 2][r] = v.z; xst[k4 * 4 + 3][r] = v.w;
    }
    __syncthreads();

    int lane = tid & 31, w = tid >> 5;
    int rb = w * 8;
    u64 acc2[4][4];                     // [row-pair][col]
#pragma unroll
    for (int m = 0; m < 4; m++)
#pragma unroll
        for (int c = 0; c < 4; c++) acc2[m][c] = 0ull;

#pragma unroll
    for (int k = 0; k < C1; k++) {
        F4U2 xa, xb;
        xa.f4 = *(float4*)&xst[k][rb];
        xb.f4 = *(float4*)&xst[k][rb + 4];
        float4 wv = *(float4*)&Ws[k][lane * 4];
        u64 wd[4];
        PACK2(wd[0], wv.x, wv.x); PACK2(wd[1], wv.y, wv.y);
        PACK2(wd[2], wv.z, wv.z); PACK2(wd[3], wv.w, wv.w);
        u64 xp[4] = {xa.u[0], xa.u[1], xb.u[0], xb.u[1]};
#pragma unroll
        for (int m = 0; m < 4; m++) {
            FMA_X2(acc2[m][0], xp[m], wd[0], acc2[m][0]);
            FMA_X2(acc2[m][1], xp[m], wd[1], acc2[m][1]);
            FMA_X2(acc2[m][2], xp[m], wd[2], acc2[m][2]);
            FMA_X2(acc2[m][3], xp[m], wd[3], acc2[m][3]);
        }
    }

    float acc[8][4];
#pragma unroll
    for (int m = 0; m < 4; m++)
#pragma unroll
        for (int c = 0; c < 4; c++)
            UNPACK2(acc[2 * m][c], acc[2 * m + 1][c], acc2[m][c]);

    float4 av = *(const float4*)&asrc[lane * 4];
    float4 bv = *(const float4*)&adst[lane * 4];
    int head = lane >> 3;
#pragma unroll
    for (int r = 0; r < 8; r++) {
        int row = row0 + rb + r;
        if (row < NN) {
            __half2 p0 = __floats2half2_rn(acc[r][0], acc[r][1]);
            __half2 p1 = __floats2half2_rn(acc[r][2], acc[r][3]);
            uint2 u;
            u.x = *reinterpret_cast<unsigned*>(&p0);
            u.y = *reinterpret_cast<unsigned*>(&p1);
            *reinterpret_cast<uint2*>(&g_h1h[row * HC1 + lane * 4]) = u;
        }
        float ps = acc[r][0] * av.x + acc[r][1] * av.y + acc[r][2] * av.z + acc[r][3] * av.w;
        float pd = acc[r][0] * bv.x + acc[r][1] * bv.y + acc[r][2] * bv.z + acc[r][3] * bv.w;
#pragma unroll
        for (int off = 4; off >= 1; off >>= 1) {
            ps += __shfl_down_sync(0xffffffffu, ps, off);
            pd += __shfl_down_sync(0xffffffffu, pd, off);
        }
        if ((lane & 7) == 0 && row < NN) {
            g_al_src1[row * H1 + head] = ps;
            g_al_dst1[row * H1 + head] = pd;
        }
    }

    // ---- fused dst histogram (memory-bound; hides under FFMA work) ----
    int is64 = sh_is64;
    int stride = gridDim.x * blockDim.x;
    for (int e = blockIdx.x * blockDim.x + tid; e < EETOT; e += stride) {
        int d;
        if (e >= EE0) d = e - EE0;
        else d = is64 ? ei[2 * (EE0 + e)] : ei[EE0 + e];
        atomicAdd(&g_degx[d], 1);
    }
}

// ---------------- fused scan: one kernel, grid-wide handoff ----------------
// 98 blocks x 1024 threads (all resident in one wave => spin is safe)
__global__ __launch_bounds__(1024) void scan_kernel() {
    __shared__ int warp_tot[32];
    __shared__ int block_base;
    int t = threadIdx.x;
    int i = blockIdx.x * 1024 + t;
    int lane = t & 31, w = t >> 5;
    int deg = (i < NN) ? g_degx[i] : 0;
    int sum = deg;
#pragma unroll
    for (int o = 1; o < 32; o <<= 1) {
        int u = __shfl_up_sync(0xffffffffu, sum, o);
        if (lane >= o) sum += u;
    }
    if (lane == 31) warp_tot[w] = sum;
    __syncthreads();
    if (w == 0) {
        int s = warp_tot[lane];
#pragma unroll
        for (int o = 1; o < 32; o <<= 1) {
            int u = __shfl_up_sync(0xffffffffu, s, o);
            if (lane >= o) s += u;
        }
        warp_tot[lane] = s;
    }
    __syncthreads();
    int wbase = (w > 0) ? warp_tot[w - 1] : 0;
    int inc = wbase + sum;              // inclusive scan within block
    if (t == 1023) g_bsum[blockIdx.x] = inc;
    __syncthreads();                    // bsum written before ticket

    // grid-wide handoff: last-arriving block scans the 98 block sums
    if (w == 0) {
        int ticket = 0;
        if (lane == 0) {
            __threadfence();
            ticket = atomicAdd(&g_degx[NN], 1);       // ticket counter
        }
        ticket = __shfl_sync(0xffffffffu, ticket, 0);
        if (ticket == NB_SCAN - 1) {
            // warp-scan of NB_SCAN block totals (4 chunks of 32 with carry)
            int carry = 0;
#pragma unroll
            for (int c = 0; c < 4; c++) {
                int idx = c * 32 + lane;
                int v = (idx < NB_SCAN) ? g_bsum[idx] : 0;
                int s = v;
#pragma unroll
                for (int o = 1; o < 32; o <<= 1) {
                    int u = __shfl_up_sync(0xffffffffu, s, o);
                    if (lane >= o) s += u;
                }
                if (idx < NB_SCAN) g_boff[idx] = carry + s - v;   // exclusive
                carry += __shfl_sync(0xffffffffu, s, 31);
            }
            __threadfence();
            if (lane == 0) atomicExch(&g_degx[NN + 1], 1);        // flag
        }
        if (lane == 0) {
            while (atomicAdd(&g_degx[NN + 1], 0) == 0) { }
            __threadfence();
            block_base = g_boff[blockIdx.x];
        }
    }
    __syncthreads();
    int base = block_base;
    if (i == 0) g_off[0] = 0;
    if (i < NN) {
        int end = base + inc;
        g_off[i + 1] = end;
        g_cursor[i] = end - deg;        // start offset; scatter bumps this
    }
}

__global__ void scatter_kernel(const int* __restrict__ ei) {
    __shared__ int sh_is64;
    if (threadIdx.x == 0) sh_is64 = detect_is64(ei);
    __syncthreads();
    int e = blockIdx.x * blockDim.x + threadIdx.x;
    if (e >= EETOT) return;
    int is64 = sh_is64;
    int s, d;
    if (e >= EE0) { s = d = e - EE0; }
    else if (is64) { s = ei[2 * e]; d = ei[2 * (EE0 + e)]; }
    else           { s = ei[e];     d = ei[EE0 + e]; }
    int pos = atomicAdd(&g_cursor[d], 1);
    g_esrc[pos] = s;
}

// ---------------- fused agg1: warp per dst node, cooperative weights ----------------
// warp = 8 edge slots x 4 heads; lane (h*8+k) computes weight of (edge k, head h)
__global__ void agg1_kernel(const float* __restrict__ b1) {
    int gid = blockIdx.x * blockDim.x + threadIdx.x;
    int d = gid >> 5;
    int lane = gid & 31;
    if (d >= NN) return;
    int h = lane >> 3;
    int esub = lane & 7;
    int grp = lane & 24;                 // h*8
    const float* __restrict__ als = g_al_src1;
    const int* __restrict__ esrc = g_esrc;
    const __half* __restrict__ h1p = g_h1h;
    float adh = g_al_dst1[d * H1 + h];
    int j0 = g_off[d], j1 = g_off[d + 1];
    float4 acc = make_float4(0.f, 0.f, 0.f, 0.f);
    float denp = 0.f;
    for (int j = j0; j < j1; j += 8) {
        int e = j + esub;
        int ec = min(e, j1 - 1);
        int s = esrc[ec];
        float as = als[s * H1 + h];
        float wgt = (e < j1) ? __expf(leaky(as + adh)) : 0.f;
        denp += wgt;
        int cnt = min(8, j1 - j);
#pragma unroll
        for (int k = 0; k < 8; k++) {
            if (k >= cnt) break;
            float wk = __shfl_sync(0xffffffffu, wgt, grp | k);
            int sk = __shfl_sync(0xffffffffu, s, grp | k);
            float a0, a1, a2, a3;
            h4load(&h1p[sk * HC1 + lane * 4], a0, a1, a2, a3);
            acc.x += wk * a0; acc.y += wk * a1;
            acc.z += wk * a2; acc.w += wk * a3;
        }
    }
    // reduce den within each 8-lane (same-head) group
    denp += __shfl_xor_sync(0xffffffffu, denp, 1);
    denp += __shfl_xor_sync(0xffffffffu, denp, 2);
    denp += __shfl_xor_sync(0xffffffffu, denp, 4);
    float inv = 1.f / denp;     // self-loop guarantees den > 0
    float4 b = *reinterpret_cast<const float4*>(&b1[lane * 4]);
    float4 o;
    o.x = acc.x * inv + b.x; o.y = acc.y * inv + b.y;
    o.z = acc.z * inv + b.z; o.w = acc.w * inv + b.w;
    o.x = o.x > 0.f ? o.x : expm1f(o.x);
    o.y = o.y > 0.f ? o.y : expm1f(o.y);
    o.z = o.z > 0.f ? o.z : expm1f(o.z);
    o.w = o.w > 0.f ? o.w : expm1f(o.w);
    __half2 p0 = __floats2half2_rn(o.x, o.y);
    __half2 p1 = __floats2half2_rn(o.z, o.w);
    uint2 u;
    u.x = *reinterpret_cast<unsigned*>(&p0);
    u.y = *reinterpret_cast<unsigned*>(&p1);
    *reinterpret_cast<uint2*>(&g_out1h[d * HC1 + lane * 4]) = u;
}

// ---------------- GEMM2 + fused logits2 ----------------
// h2[N,32] = out1[N,128] @ W2[128,32]
#define G2_ROWS 64
__global__ __launch_bounds__(256) void gemm2_kernel(const float* __restrict__ W2,
                                                    const float* __restrict__ asrc,
                                                    const float* __restrict__ adst) {
    __shared__ float xst[HC1][G2_ROWS];  // 32 KB
    __shared__ float Ws[HC1][OUTC];      // 16 KB
    int tid = threadIdx.x;
    int row0 = blockIdx.x * G2_ROWS;

    const float4* W4 = (const float4*)W2;
    float4* Ws4 = (float4*)Ws;
#pragma unroll
    for (int i = 0; i < 4; i++) Ws4[tid + 256 * i] = W4[tid + 256 * i];
#pragma unroll
    for (int i = 0; i < 4; i++) {
        int idx = tid + 256 * i;          // uint4 (8 halves) idx; 16 per row
        int r = idx >> 4, k8 = idx & 15;
        int row = row0 + r;
        uint4 v = make_uint4(0u, 0u, 0u, 0u);
        if (row < NN) v = *(const uint4*)&g_out1h[row * HC1 + k8 * 8];
        const unsigned uu[4] = {v.x, v.y, v.z, v.w};
#pragma unroll
        for (int q = 0; q < 4; q++) {
            __half2 hh = *reinterpret_cast<const __half2*>(&uu[q]);
            float2 ff = __half22float2(hh);
            xst[k8 * 8 + q * 2 + 0][r] = ff.x;
            xst[k8 * 8 + q * 2 + 1][r] = ff.y;
        }
    }
    __syncthreads();

    int lane = tid & 31, w = tid >> 5;
    int rb = w * 8;
    u64 acc2[4];
#pragma unroll
    for (int m = 0; m < 4; m++) acc2[m] = 0ull;
#pragma unroll
    for (int k = 0; k < HC1; k++) {
        F4U2 xa, xb;
        xa.f4 = *(float4*)&xst[k][rb];
        xb.f4 = *(float4*)&xst[k][rb + 4];
        float wv = Ws[k][lane];
        u64 wd;
        PACK2(wd, wv, wv);
        FMA_X2(acc2[0], xa.u[0], wd, acc2[0]);
        FMA_X2(acc2[1], xa.u[1], wd, acc2[1]);
        FMA_X2(acc2[2], xb.u[0], wd, acc2[2]);
        FMA_X2(acc2[3], xb.u[1], wd, acc2[3]);
    }
    float acc[8];
#pragma unroll
    for (int m = 0; m < 4; m++) UNPACK2(acc[2 * m], acc[2 * m + 1], acc2[m]);

    float av = asrc[lane], bv = adst[lane];
#pragma unroll
    for (int r = 0; r < 8; r++) {
        int row = row0 + rb + r;
        if (row < NN) g_h2h[row * OUTC + lane] = __float2half_rn(acc[r]);
        float ps = acc[r] * av;
        float pd = acc[r] * bv;
#pragma unroll
        for (int off = 16; off >= 1; off >>= 1) {
            ps += __shfl_down_sync(0xffffffffu, ps, off);
            pd += __shfl_down_sync(0xffffffffu, pd, off);
        }
        if (lane == 0 && row < NN) {
            g_al_src2[row] = ps;
            g_al_dst2[row] = pd;
        }
    }
}

// ---------------- fused agg2: warp per dst node, cooperative weights ----------------
__global__ void agg2_kernel(float* __restrict__ dout, const float* __restrict__ b2) {
    int gid = blockIdx.x * blockDim.x + threadIdx.x;
    int d = gid >> 5;
    int lane = gid & 31;
    if (d >= NN) return;
    const float* __restrict__ als = g_al_src2;
    const int* __restrict__ esrc = g_esrc;
    const __half* __restrict__ h2p = g_h2h;
    float ad2 = g_al_dst2[d];
    int j0 = g_off[d], j1 = g_off[d + 1];
    float acc = 0.f, denp = 0.f;
    for (int j = j0; j < j1; j += 32) {
        int e = j + lane;
        int ec = min(e, j1 - 1);
        int s = esrc[ec];
        float wgt = (e < j1) ? __expf(leaky(als[s] + ad2)) : 0.f;
        denp += wgt;
        int cnt = min(32, j1 - j);
#pragma unroll 8
        for (int k = 0; k < cnt; k++) {
            float wk = __shfl_sync(0xffffffffu, wgt, k);
            int sk = __shfl_sync(0xffffffffu, s, k);
            acc += wk * __half2float(h2p[sk * OUTC + lane]);
        }
    }
#pragma unroll
    for (int o = 16; o >= 1; o >>= 1)
        denp += __shfl_xor_sync(0xffffffffu, denp, o);
    dout[d * OUTC + lane] = acc / denp + b2[lane];
}

// ---------------- launch ----------------
extern "C" void kernel_launch(void* const* d_in, const int* in_sizes, int n_in,
                              void* d_out, int out_size) {
    const float* x        = (const float*)d_in[0];
    const int*   ei       = (const int*)d_in[1];
    const float* W1       = (const float*)d_in[2];
    const float* att_src1 = (const float*)d_in[3];
    const float* att_dst1 = (const float*)d_in[4];
    const float* b1       = (const float*)d_in[5];
    const float* W2       = (const float*)d_in[6];
    const float* att_src2 = (const float*)d_in[7];
    const float* att_dst2 = (const float*)d_in[8];
    const float* b2       = (const float*)d_in[9];
    float* dout = (float*)d_out;

    const int T = 256;
    void* degx_ptr = nullptr;
    cudaGetSymbolAddress(&degx_ptr, g_degx);
    cudaMemsetAsync(degx_ptr, 0, (NN + 2) * sizeof(int));

    gemm1_kernel<<<(NN + G1_ROWS - 1) / G1_ROWS, 256>>>(x, W1, att_src1, att_dst1, ei);
    scan_kernel<<<NB_SCAN, 1024>>>();
    scatter_kernel<<<(EETOT + T - 1) / T, T>>>(ei);
    agg1_kernel<<<(NN * 32 + T - 1) / T, T>>>(b1);

    gemm2_kernel<<<(NN + G2_ROWS - 1) / G2_ROWS, 256>>>(W2, att_src2, att_dst2);
    agg2_kernel<<<(NN * 32 + T - 1) / T, T>>>(dout, b2);
}

// round 8
// speedup vs baseline: 1.1146x; 1.1146x over previous
#include <cuda_runtime.h>
#include <cuda_fp16.h>
#include <math.h>

// ---------------- problem constants ----------------
#define NN   100000
#define EE0  1600000            // raw edges
#define EETOT (EE0 + NN)        // + self loops
#define C1   64                 // in channels
#define H1   4                  // heads layer1
#define HC1  128                // H1*D1
#define OUTC 32                 // layer2 out channels
#define NB_SCAN 98              // ceil(NN/1024)
#define LOG2E 1.4426950408889634f

typedef unsigned long long u64;
#define FMA_X2(d, a, b, c) \
    asm("fma.rn.f32x2 %0, %1, %2, %3;" : "=l"(d) : "l"(a), "l"(b), "l"(c))
#define PACK2(d, lo, hi) \
    asm("mov.b64 %0, {%1, %2};" : "=l"(d) : "f"(lo), "f"(hi))
#define UNPACK2(lo, hi, s) \
    asm("mov.b64 {%0, %1}, %2;" : "=f"(lo), "=f"(hi) : "l"(s))

union F4U2 { float4 f4; u64 u[2]; };

// ---------------- scratch (device globals; no allocation) ----------------
__device__ __half g_h1h[NN * HC1];      // layer1 features (fp16, gather-only)
__device__ __half g_out1h[NN * HC1];    // elu(agg1 + b1) (fp16, gemm2 input)
__device__ float  g_al_src1[NN * H1];   // pre-scaled by log2(e)
__device__ float  g_al_dst1[NN * H1];

__device__ float  g_h2f[NN * OUTC];     // layer2 features (fp32, L2-resident)
__device__ float  g_al_src2[NN];        // pre-scaled by log2(e)
__device__ float  g_al_dst2[NN];

// CSR build: g_degx = [deg[NN], ticket1, flag1, ticket2, flag2]
__device__ int g_degx[NN + 4];
__device__ int g_cursor[NN];
__device__ int g_bsum[NB_SCAN];
__device__ int g_boff[NB_SCAN];
__device__ int g_off[NN + 1];
__device__ int g_esrc[EETOT];

// ---------------- helpers ----------------
__device__ __forceinline__ float ex2(float x) {
    float r;
    asm("ex2.approx.ftz.f32 %0, %1;" : "=f"(r) : "f"(x));
    return r;
}
// weight from pre-scaled logit sum: 2^(leaky(x))
__device__ __forceinline__ float wfun(float x) {
    return ex2(fmaxf(x, 0.2f * x));
}

// int64 little-endian edges => int32 view has zero high words (indices < 2^31)
__device__ __forceinline__ int detect_is64(const int* __restrict__ ei) {
    int zeros = 0;
#pragma unroll
    for (int k = 0; k < 16; k++) zeros += (ei[2 * k + 1] == 0);
    return zeros == 16;
}

__device__ __forceinline__ void h4load(const __half* p, float& f0, float& f1,
                                       float& f2, float& f3) {
    uint2 u = *reinterpret_cast<const uint2*>(p);
    __half2 a = *reinterpret_cast<__half2*>(&u.x);
    __half2 b = *reinterpret_cast<__half2*>(&u.y);
    float2 fa = __half22float2(a), fb = __half22float2(b);
    f0 = fa.x; f1 = fa.y; f2 = fb.x; f3 = fb.y;
}

// ---------------- GEMM1 + fused logits1 + fused dst histogram ----------------
#define G1_ROWS 64
__global__ __launch_bounds__(256) void gemm1_kernel(const float* __restrict__ x,
                                                    const float* __restrict__ W,
                                                    const float* __restrict__ asrc,
                                                    const float* __restrict__ adst,
                                                    const int* __restrict__ ei) {
    __shared__ float xst[C1][G1_ROWS];   // [k][row] 16 KB
    __shared__ float Ws[C1][HC1];        // 32 KB
    __shared__ int sh_is64;
    int tid = threadIdx.x;
    int row0 = blockIdx.x * G1_ROWS;
    if (tid == 0) sh_is64 = detect_is64(ei);

    const float4* W4 = (const float4*)W;
    float4* Ws4 = (float4*)Ws;
#pragma unroll
    for (int i = 0; i < 8; i++) Ws4[tid + 256 * i] = W4[tid + 256 * i];
#pragma unroll
    for (int i = 0; i < 4; i++) {
        int idx = tid + 256 * i;          // float4 idx; 16 per row
        int r = idx >> 4, k4 = idx & 15;
        int row = row0 + r;
        float4 v = make_float4(0.f, 0.f, 0.f, 0.f);
        if (row < NN) v = *(const float4*)&x[row * C1 + k4 * 4];
        xst[k4 * 4 + 0][r] = v.x; xst[k4 * 4 + 1][r] = v.y;
        xst[k4 * 4 + 2][r] = v.z; xst[k4 * 4 + 3][r] = v.w;
    }
    __syncthreads();

    int lane = tid & 31, w = tid >> 5;
    int rb = w * 8;
    u64 acc2[4][4];                     // [row-pair][col]
#pragma unroll
    for (int m = 0; m < 4; m++)
#pragma unroll
        for (int c = 0; c < 4; c++) acc2[m][c] = 0ull;

#pragma unroll
    for (int k = 0; k < C1; k++) {
        F4U2 xa, xb;
        xa.f4 = *(float4*)&xst[k][rb];
        xb.f4 = *(float4*)&xst[k][rb + 4];
        float4 wv = *(float4*)&Ws[k][lane * 4];
        u64 wd[4];
        PACK2(wd[0], wv.x, wv.x); PACK2(wd[1], wv.y, wv.y);
        PACK2(wd[2], wv.z, wv.z); PACK2(wd[3], wv.w, wv.w);
        u64 xp[4] = {xa.u[0], xa.u[1], xb.u[0], xb.u[1]};
#pragma unroll
        for (int m = 0; m < 4; m++) {
            FMA_X2(acc2[m][0], xp[m], wd[0], acc2[m][0]);
            FMA_X2(acc2[m][1], xp[m], wd[1], acc2[m][1]);
            FMA_X2(acc2[m][2], xp[m], wd[2], acc2[m][2]);
            FMA_X2(acc2[m][3], xp[m], wd[3], acc2[m][3]);
        }
    }

    float acc[8][4];
#pragma unroll
    for (int m = 0; m < 4; m++)
#pragma unroll
        for (int c = 0; c < 4; c++)
            UNPACK2(acc[2 * m][c], acc[2 * m + 1][c], acc2[m][c]);

    float4 av = *(const float4*)&asrc[lane * 4];
    float4 bv = *(const float4*)&adst[lane * 4];
    int head = lane >> 3;
#pragma unroll
    for (int r = 0; r < 8; r++) {
        int row = row0 + rb + r;
        if (row < NN) {
            __half2 p0 = __floats2half2_rn(acc[r][0], acc[r][1]);
            __half2 p1 = __floats2half2_rn(acc[r][2], acc[r][3]);
            uint2 u;
            u.x = *reinterpret_cast<unsigned*>(&p0);
            u.y = *reinterpret_cast<unsigned*>(&p1);
            *reinterpret_cast<uint2*>(&g_h1h[row * HC1 + lane * 4]) = u;
        }
        float ps = acc[r][0] * av.x + acc[r][1] * av.y + acc[r][2] * av.z + acc[r][3] * av.w;
        float pd = acc[r][0] * bv.x + acc[r][1] * bv.y + acc[r][2] * bv.z + acc[r][3] * bv.w;
#pragma unroll
        for (int off = 4; off >= 1; off >>= 1) {
            ps += __shfl_down_sync(0xffffffffu, ps, off);
            pd += __shfl_down_sync(0xffffffffu, pd, off);
        }
        if ((lane & 7) == 0 && row < NN) {
            g_al_src1[row * H1 + head] = ps * LOG2E;
            g_al_dst1[row * H1 + head] = pd * LOG2E;
        }
    }

    // ---- fused dst histogram (memory-bound; hides under FFMA work) ----
    int is64 = sh_is64;
    int stride = gridDim.x * blockDim.x;
    for (int e = blockIdx.x * blockDim.x + tid; e < EETOT; e += stride) {
        int d;
        if (e >= EE0) d = e - EE0;
        else d = is64 ? ei[2 * (EE0 + e)] : ei[EE0 + e];
        atomicAdd(&g_degx[d], 1);
    }
}

// ---------------- fused scan + scatter: one kernel, two grid-wide handoffs ----
// 98 blocks x 1024 threads (all resident in one wave => spin is safe)
__global__ __launch_bounds__(1024) void scan_kernel(const int* __restrict__ ei) {
    __shared__ int warp_tot[32];
    __shared__ int block_base;
    __shared__ int sh_is64;
    int t = threadIdx.x;
    int i = blockIdx.x * 1024 + t;
    int lane = t & 31, w = t >> 5;
    if (t == 0) sh_is64 = detect_is64(ei);
    int deg = (i < NN) ? g_degx[i] : 0;
    int sum = deg;
#pragma unroll
    for (int o = 1; o < 32; o <<= 1) {
        int u = __shfl_up_sync(0xffffffffu, sum, o);
        if (lane >= o) sum += u;
    }
    if (lane == 31) warp_tot[w] = sum;
    __syncthreads();
    if (w == 0) {
        int s = warp_tot[lane];
#pragma unroll
        for (int o = 1; o < 32; o <<= 1) {
            int u = __shfl_up_sync(0xffffffffu, s, o);
            if (lane >= o) s += u;
        }
        warp_tot[lane] = s;
    }
    __syncthreads();
    int wbase = (w > 0) ? warp_tot[w - 1] : 0;
    int inc = wbase + sum;              // inclusive scan within block
    if (t == 1023) g_bsum[blockIdx.x] = inc;
    __syncthreads();                    // bsum written before ticket

    // grid-wide handoff 1: last-arriving block scans the 98 block sums
    if (w == 0) {
        int ticket = 0;
        if (lane == 0) {
            __threadfence();
            ticket = atomicAdd(&g_degx[NN], 1);
        }
        ticket = __shfl_sync(0xffffffffu, ticket, 0);
        if (ticket == NB_SCAN - 1) {
            int carry = 0;
#pragma unroll
            for (int c = 0; c < 4; c++) {
                int idx = c * 32 + lane;
                int v = (idx < NB_SCAN) ? g_bsum[idx] : 0;
                int s = v;
#pragma unroll
                for (int o = 1; o < 32; o <<= 1) {
                    int u = __shfl_up_sync(0xffffffffu, s, o);
                    if (lane >= o) s += u;
                }
                if (idx < NB_SCAN) g_boff[idx] = carry + s - v;   // exclusive
                carry += __shfl_sync(0xffffffffu, s, 31);
            }
            __threadfence();
            if (lane == 0) atomicExch(&g_degx[NN + 1], 1);
        }
        if (lane == 0) {
            while (atomicAdd(&g_degx[NN + 1], 0) == 0) { }
            __threadfence();
            block_base = g_boff[blockIdx.x];
        }
    }
    __syncthreads();
    int base = block_base;
    if (i == 0) g_off[0] = 0;
    if (i < NN) {
        int end = base + inc;
        g_off[i + 1] = end;
        g_cursor[i] = end - deg;        // start offset; scatter bumps this
    }

    // grid-wide handoff 2: all cursors visible before scatter
    __syncthreads();
    if (t == 0) {
        __threadfence();
        int t2 = atomicAdd(&g_degx[NN + 2], 1);
        if (t2 == NB_SCAN - 1) atomicExch(&g_degx[NN + 3], 1);
        while (atomicAdd(&g_degx[NN + 3], 0) == 0) { }
        __threadfence();
    }
    __syncthreads();

    // ---- scatter (grid-stride) ----
    int is64 = sh_is64;
    for (int e = blockIdx.x * 1024 + t; e < EETOT; e += NB_SCAN * 1024) {
        int s, d;
        if (e >= EE0) { s = d = e - EE0; }
        else if (is64) { s = ei[2 * e]; d = ei[2 * (EE0 + e)]; }
        else           { s = ei[e];     d = ei[EE0 + e]; }
        int pos = atomicAdd(&g_cursor[d], 1);
        g_esrc[pos] = s;
    }
}

// ---------------- fused agg1: warp per dst node, CSR, no atomics ----------------
__global__ void agg1_kernel(const float* __restrict__ b1) {
    int gid = blockIdx.x * blockDim.x + threadIdx.x;
    int d = gid >> 5;
    int lane = gid & 31;
    if (d >= NN) return;
    int h = lane >> 3;
    const float* __restrict__ als = g_al_src1;
    const int* __restrict__ esrc = g_esrc;
    const __half* __restrict__ h1p = g_h1h;
    float adh = g_al_dst1[d * H1 + h];
    int j0 = g_off[d], j1 = g_off[d + 1];
    float4 acc = make_float4(0.f, 0.f, 0.f, 0.f);
    float den = 0.f;
    int j = j0;
    for (; j + 3 < j1; j += 4) {
        int s0 = esrc[j],     s1 = esrc[j + 1];
        int s2 = esrc[j + 2], s3 = esrc[j + 3];
        float x0 = als[s0 * H1 + h] + adh;
        float x1 = als[s1 * H1 + h] + adh;
        float x2 = als[s2 * H1 + h] + adh;
        float x3 = als[s3 * H1 + h] + adh;
        float a0, a1, a2, a3, c0, c1, c2, c3;
        float e0, e1, e2, e3, f0, f1, f2, f3;
        h4load(&h1p[s0 * HC1 + lane * 4], a0, a1, a2, a3);
        h4load(&h1p[s1 * HC1 + lane * 4], c0, c1, c2, c3);
        h4load(&h1p[s2 * HC1 + lane * 4], e0, e1, e2, e3);
        h4load(&h1p[s3 * HC1 + lane * 4], f0, f1, f2, f3);
        float w0 = wfun(x0), w1 = wfun(x1), w2 = wfun(x2), w3 = wfun(x3);
        den += (w0 + w1) + (w2 + w3);
        acc.x += w0 * a0 + w1 * c0 + w2 * e0 + w3 * f0;
        acc.y += w0 * a1 + w1 * c1 + w2 * e1 + w3 * f1;
        acc.z += w0 * a2 + w1 * c2 + w2 * e2 + w3 * f2;
        acc.w += w0 * a3 + w1 * c3 + w2 * e3 + w3 * f3;
    }
    for (; j < j1; j++) {
        int s0 = esrc[j];
        float x0 = als[s0 * H1 + h] + adh;
        float a0, a1, a2, a3;
        h4load(&h1p[s0 * HC1 + lane * 4], a0, a1, a2, a3);
        float w0 = wfun(x0);
        den += w0;
        acc.x += w0 * a0; acc.y += w0 * a1;
        acc.z += w0 * a2; acc.w += w0 * a3;
    }
    float inv = 1.f / den;      // self-loop guarantees den > 0
    float4 b = *reinterpret_cast<const float4*>(&b1[lane * 4]);
    float4 o;
    o.x = acc.x * inv + b.x; o.y = acc.y * inv + b.y;
    o.z = acc.z * inv + b.z; o.w = acc.w * inv + b.w;
    o.x = o.x > 0.f ? o.x : expm1f(o.x);
    o.y = o.y > 0.f ? o.y : expm1f(o.y);
    o.z = o.z > 0.f ? o.z : expm1f(o.z);
    o.w = o.w > 0.f ? o.w : expm1f(o.w);
    __half2 p0 = __floats2half2_rn(o.x, o.y);
    __half2 p1 = __floats2half2_rn(o.z, o.w);
    uint2 u;
    u.x = *reinterpret_cast<unsigned*>(&p0);
    u.y = *reinterpret_cast<unsigned*>(&p1);
    *reinterpret_cast<uint2*>(&g_out1h[d * HC1 + lane * 4]) = u;
}

// ---------------- GEMM2 + fused logits2 ----------------
#define G2_ROWS 64
__global__ __launch_bounds__(256) void gemm2_kernel(const float* __restrict__ W2,
                                                    const float* __restrict__ asrc,
                                                    const float* __restrict__ adst) {
    __shared__ float xst[HC1][G2_ROWS];  // 32 KB
    __shared__ float Ws[HC1][OUTC];      // 16 KB
    int tid = threadIdx.x;
    int row0 = blockIdx.x * G2_ROWS;

    const float4* W4 = (const float4*)W2;
    float4* Ws4 = (float4*)Ws;
#pragma unroll
    for (int i = 0; i < 4; i++) Ws4[tid + 256 * i] = W4[tid + 256 * i];
#pragma unroll
    for (int i = 0; i < 4; i++) {
        int idx = tid + 256 * i;          // uint4 (8 halves) idx; 16 per row
        int r = idx >> 4, k8 = idx & 15;
        int row = row0 + r;
        uint4 v = make_uint4(0u, 0u, 0u, 0u);
        if (row < NN) v = *(const uint4*)&g_out1h[row * HC1 + k8 * 8];
        const unsigned uu[4] = {v.x, v.y, v.z, v.w};
#pragma unroll
        for (int q = 0; q < 4; q++) {
            __half2 hh = *reinterpret_cast<const __half2*>(&uu[q]);
            float2 ff = __half22float2(hh);
            xst[k8 * 8 + q * 2 + 0][r] = ff.x;
            xst[k8 * 8 + q * 2 + 1][r] = ff.y;
        }
    }
    __syncthreads();

    int lane = tid & 31, w = tid >> 5;
    int rb = w * 8;
    u64 acc2[4];
#pragma unroll
    for (int m = 0; m < 4; m++) acc2[m] = 0ull;
#pragma unroll
    for (int k = 0; k < HC1; k++) {
        F4U2 xa, xb;
        xa.f4 = *(float4*)&xst[k][rb];
        xb.f4 = *(float4*)&xst[k][rb + 4];
        float wv = Ws[k][lane];
        u64 wd;
        PACK2(wd, wv, wv);
        FMA_X2(acc2[0], xa.u[0], wd, acc2[0]);
        FMA_X2(acc2[1], xa.u[1], wd, acc2[1]);
        FMA_X2(acc2[2], xb.u[0], wd, acc2[2]);
        FMA_X2(acc2[3], xb.u[1], wd, acc2[3]);
    }
    float acc[8];
#pragma unroll
    for (int m = 0; m < 4; m++) UNPACK2(acc[2 * m], acc[2 * m + 1], acc2[m]);

    float av = asrc[lane], bv = adst[lane];
#pragma unroll
    for (int r = 0; r < 8; r++) {
        int row = row0 + rb + r;
        if (row < NN) g_h2f[row * OUTC + lane] = acc[r];
        float ps = acc[r] * av;
        float pd = acc[r] * bv;
#pragma unroll
        for (int off = 16; off >= 1; off >>= 1) {
            ps += __shfl_down_sync(0xffffffffu, ps, off);
            pd += __shfl_down_sync(0xffffffffu, pd, off);
        }
        if (lane == 0 && row < NN) {
            g_al_src2[row] = ps * LOG2E;
            g_al_dst2[row] = pd * LOG2E;
        }
    }
}

// ---------------- fused agg2: warp per dst node ----------------
__global__ void agg2_kernel(float* __restrict__ dout, const float* __restrict__ b2) {
    int gid = blockIdx.x * blockDim.x + threadIdx.x;
    int d = gid >> 5;
    int lane = gid & 31;
    if (d >= NN) return;
    const float* __restrict__ als = g_al_src2;
    const int* __restrict__ esrc = g_esrc;
    const float* __restrict__ h2p = g_h2f;
    float ad2 = g_al_dst2[d];
    int j0 = g_off[d], j1 = g_off[d + 1];
    float acc = 0.f, den = 0.f;
    int j = j0;
    for (; j + 3 < j1; j += 4) {
        int s0 = esrc[j],     s1 = esrc[j + 1];
        int s2 = esrc[j + 2], s3 = esrc[j + 3];
        float x0 = als[s0] + ad2, x1 = als[s1] + ad2;
        float x2 = als[s2] + ad2, x3 = als[s3] + ad2;
        float v0 = h2p[s0 * OUTC + lane];
        float v1 = h2p[s1 * OUTC + lane];
        float v2 = h2p[s2 * OUTC + lane];
        float v3 = h2p[s3 * OUTC + lane];
        float w0 = wfun(x0), w1 = wfun(x1), w2 = wfun(x2), w3 = wfun(x3);
        den += (w0 + w1) + (w2 + w3);
        acc += w0 * v0 + w1 * v1 + w2 * v2 + w3 * v3;
    }
    for (; j < j1; j++) {
        int s0 = esrc[j];
        float w0 = wfun(als[s0] + ad2);
        den += w0;
        acc += w0 * h2p[s0 * OUTC + lane];
    }
    dout[d * OUTC + lane] = acc / den + b2[lane];
}

// ---------------- launch ----------------
extern "C" void kernel_launch(void* const* d_in, const int* in_sizes, int n_in,
                              void* d_out, int out_size) {
    const float* x        = (const float*)d_in[0];
    const int*   ei       = (const int*)d_in[1];
    const float* W1       = (const float*)d_in[2];
    const float* att_src1 = (const float*)d_in[3];
    const float* att_dst1 = (const float*)d_in[4];
    const float* b1       = (const float*)d_in[5];
    const float* W2       = (const float*)d_in[6];
    const float* att_src2 = (const float*)d_in[7];
    const float* att_dst2 = (const float*)d_in[8];
    const float* b2       = (const float*)d_in[9];
    float* dout = (float*)d_out;

    const int T = 256;
    void* degx_ptr = nullptr;
    cudaGetSymbolAddress(&degx_ptr, g_degx);
    cudaMemsetAsync(degx_ptr, 0, (NN + 4) * sizeof(int));

    gemm1_kernel<<<(NN + G1_ROWS - 1) / G1_ROWS, 256>>>(x, W1, att_src1, att_dst1, ei);
    scan_kernel<<<NB_SCAN, 1024>>>(ei);
    agg1_kernel<<<(NN * 32 + T - 1) / T, T>>>(b1);

    gemm2_kernel<<<(NN + G2_ROWS - 1) / G2_ROWS, 256>>>(W2, att_src2, att_dst2);
    agg2_kernel<<<(NN * 32 + T - 1) / T, T>>>(dout, b2);
}

// round 9
// speedup vs baseline: 1.1825x; 1.0609x over previous
#include <cuda_runtime.h>
#include <cuda_fp16.h>
#include <math.h>

// ---------------- problem constants ----------------
#define NN   100000
#define EE0  1600000            // raw edges
#define EETOT (EE0 + NN)        // + self loops
#define C1   64                 // in channels
#define H1   4                  // heads layer1
#define HC1  128                // H1*D1
#define OUTC 32                 // layer2 out channels
#define NB_SCAN 98              // ceil(NN/1024)
#define LOG2E 1.4426950408889634f

typedef unsigned long long u64;
#define FMA_X2(d, a, b, c) \
    asm("fma.rn.f32x2 %0, %1, %2, %3;" : "=l"(d) : "l"(a), "l"(b), "l"(c))
#define PACK2(d, lo, hi) \
    asm("mov.b64 %0, {%1, %2};" : "=l"(d) : "f"(lo), "f"(hi))
#define UNPACK2(lo, hi, s) \
    asm("mov.b64 {%0, %1}, %2;" : "=f"(lo), "=f"(hi) : "l"(s))

union F4U2 { float4 f4; u64 u[2]; };

// ---------------- scratch (device globals; no allocation) ----------------
__device__ __half g_h1h[NN * HC1];      // layer1 features (fp16, gather-only)
__device__ __half g_out1h[NN * HC1];    // elu(agg1 + b1) (fp16, gemm2 input)
__device__ float  g_al_src1[NN * H1];   // pre-scaled by log2(e)
__device__ float  g_al_dst1[NN * H1];

__device__ float  g_h2f[NN * OUTC];     // layer2 features (fp32, L2-resident)
__device__ float  g_al_src2[NN];        // pre-scaled by log2(e)
__device__ float  g_al_dst2[NN];

// CSR build: g_degx = [deg[NN], ticket1, flag1, ticket2, flag2]
__device__ int g_degx[NN + 4];
__device__ int g_cursor[NN];
__device__ int g_bsum[NB_SCAN];
__device__ int g_boff[NB_SCAN];
__device__ int g_off[NN + 1];
__device__ int g_esrc[EETOT];

// ---------------- helpers ----------------
__device__ __forceinline__ float ex2(float x) {
    float r;
    asm("ex2.approx.ftz.f32 %0, %1;" : "=f"(r) : "f"(x));
    return r;
}
// weight from pre-scaled logit sum: 2^(leaky(x))
__device__ __forceinline__ float wfun(float x) {
    return ex2(fmaxf(x, 0.2f * x));
}

// int64 little-endian edges => int32 view has zero high words (indices < 2^31)
__device__ __forceinline__ int detect_is64(const int* __restrict__ ei) {
    int zeros = 0;
#pragma unroll
    for (int k = 0; k < 16; k++) zeros += (ei[2 * k + 1] == 0);
    return zeros == 16;
}

__device__ __forceinline__ void h4load(const __half* p, float& f0, float& f1,
                                       float& f2, float& f3) {
    uint2 u = *reinterpret_cast<const uint2*>(p);
    __half2 a = *reinterpret_cast<__half2*>(&u.x);
    __half2 b = *reinterpret_cast<__half2*>(&u.y);
    float2 fa = __half22float2(a), fb = __half22float2(b);
    f0 = fa.x; f1 = fa.y; f2 = fb.x; f3 = fb.y;
}

// ---------------- GEMM1 + fused logits1 + fused dst histogram ----------------
#define G1_ROWS 64
__global__ __launch_bounds__(256) void gemm1_kernel(const float* __restrict__ x,
                                                    const float* __restrict__ W,
                                                    const float* __restrict__ asrc,
                                                    const float* __restrict__ adst,
                                                    const int* __restrict__ ei) {
    __shared__ float xst[C1][G1_ROWS];   // [k][row] 16 KB
    __shared__ float Ws[C1][HC1];        // 32 KB
    __shared__ int sh_is64;
    int tid = threadIdx.x;
    int row0 = blockIdx.x * G1_ROWS;
    if (tid == 0) sh_is64 = detect_is64(ei);

    const float4* W4 = (const float4*)W;
    float4* Ws4 = (float4*)Ws;
#pragma unroll
    for (int i = 0; i < 8; i++) Ws4[tid + 256 * i] = W4[tid + 256 * i];
#pragma unroll
    for (int i = 0; i < 4; i++) {
        int idx = tid + 256 * i;          // float4 idx; 16 per row
        int r = idx >> 4, k4 = idx & 15;
        int row = row0 + r;
        float4 v = make_float4(0.f, 0.f, 0.f, 0.f);
        if (row < NN) v = *(const float4*)&x[row * C1 + k4 * 4];
        xst[k4 * 4 + 0][r] = v.x; xst[k4 * 4 + 1][r] = v.y;
        xst[k4 * 4 + 2][r] = v.z; xst[k4 * 4 + 3][r] = v.w;
    }
    __syncthreads();

    int lane = tid & 31, w = tid >> 5;
    int rb = w * 8;
    u64 acc2[4][4];                     // [row-pair][col]
#pragma unroll
    for (int m = 0; m < 4; m++)
#pragma unroll
        for (int c = 0; c < 4; c++) acc2[m][c] = 0ull;

#pragma unroll
    for (int k = 0; k < C1; k++) {
        F4U2 xa, xb;
        xa.f4 = *(float4*)&xst[k][rb];
        xb.f4 = *(float4*)&xst[k][rb + 4];
        float4 wv = *(float4*)&Ws[k][lane * 4];
        u64 wd[4];
        PACK2(wd[0], wv.x, wv.x); PACK2(wd[1], wv.y, wv.y);
        PACK2(wd[2], wv.z, wv.z); PACK2(wd[3], wv.w, wv.w);
        u64 xp[4] = {xa.u[0], xa.u[1], xb.u[0], xb.u[1]};
#pragma unroll
        for (int m = 0; m < 4; m++) {
            FMA_X2(acc2[m][0], xp[m], wd[0], acc2[m][0]);
            FMA_X2(acc2[m][1], xp[m], wd[1], acc2[m][1]);
            FMA_X2(acc2[m][2], xp[m], wd[2], acc2[m][2]);
            FMA_X2(acc2[m][3], xp[m], wd[3], acc2[m][3]);
        }
    }

    float acc[8][4];
#pragma unroll
    for (int m = 0; m < 4; m++)
#pragma unroll
        for (int c = 0; c < 4; c++)
            UNPACK2(acc[2 * m][c], acc[2 * m + 1][c], acc2[m][c]);

    float4 av = *(const float4*)&asrc[lane * 4];
    float4 bv = *(const float4*)&adst[lane * 4];
    int head = lane >> 3;
#pragma unroll
    for (int r = 0; r < 8; r++) {
        int row = row0 + rb + r;
        if (row < NN) {
            __half2 p0 = __floats2half2_rn(acc[r][0], acc[r][1]);
            __half2 p1 = __floats2half2_rn(acc[r][2], acc[r][3]);
            uint2 u;
            u.x = *reinterpret_cast<unsigned*>(&p0);
            u.y = *reinterpret_cast<unsigned*>(&p1);
            *reinterpret_cast<uint2*>(&g_h1h[row * HC1 + lane * 4]) = u;
        }
        float ps = acc[r][0] * av.x + acc[r][1] * av.y + acc[r][2] * av.z + acc[r][3] * av.w;
        float pd = acc[r][0] * bv.x + acc[r][1] * bv.y + acc[r][2] * bv.z + acc[r][3] * bv.w;
#pragma unroll
        for (int off = 4; off >= 1; off >>= 1) {
            ps += __shfl_down_sync(0xffffffffu, ps, off);
            pd += __shfl_down_sync(0xffffffffu, pd, off);
        }
        if ((lane & 7) == 0 && row < NN) {
            g_al_src1[row * H1 + head] = ps * LOG2E;
            g_al_dst1[row * H1 + head] = pd * LOG2E;
        }
    }

    // ---- fused dst histogram (memory-bound; hides under FFMA work) ----
    int is64 = sh_is64;
    int stride = gridDim.x * blockDim.x;
    for (int e = blockIdx.x * blockDim.x + tid; e < EETOT; e += stride) {
        int d;
        if (e >= EE0) d = e - EE0;
        else d = is64 ? ei[2 * (EE0 + e)] : ei[EE0 + e];
        atomicAdd(&g_degx[d], 1);
    }
}

// ---------------- fused scan + scatter: one kernel, two grid-wide handoffs ----
__global__ __launch_bounds__(1024) void scan_kernel(const int* __restrict__ ei) {
    __shared__ int warp_tot[32];
    __shared__ int block_base;
    __shared__ int sh_is64;
    int t = threadIdx.x;
    int i = blockIdx.x * 1024 + t;
    int lane = t & 31, w = t >> 5;
    if (t == 0) sh_is64 = detect_is64(ei);
    int deg = (i < NN) ? g_degx[i] : 0;
    int sum = deg;
#pragma unroll
    for (int o = 1; o < 32; o <<= 1) {
        int u = __shfl_up_sync(0xffffffffu, sum, o);
        if (lane >= o) sum += u;
    }
    if (lane == 31) warp_tot[w] = sum;
    __syncthreads();
    if (w == 0) {
        int s = warp_tot[lane];
#pragma unroll
        for (int o = 1; o < 32; o <<= 1) {
            int u = __shfl_up_sync(0xffffffffu, s, o);
            if (lane >= o) s += u;
        }
        warp_tot[lane] = s;
    }
    __syncthreads();
    int wbase = (w > 0) ? warp_tot[w - 1] : 0;
    int inc = wbase + sum;              // inclusive scan within block
    if (t == 1023) g_bsum[blockIdx.x] = inc;
    __syncthreads();                    // bsum written before ticket

    if (w == 0) {
        int ticket = 0;
        if (lane == 0) {
            __threadfence();
            ticket = atomicAdd(&g_degx[NN], 1);
        }
        ticket = __shfl_sync(0xffffffffu, ticket, 0);
        if (ticket == NB_SCAN - 1) {
            int carry = 0;
#pragma unroll
            for (int c = 0; c < 4; c++) {
                int idx = c * 32 + lane;
                int v = (idx < NB_SCAN) ? g_bsum[idx] : 0;
                int s = v;
#pragma unroll
                for (int o = 1; o < 32; o <<= 1) {
                    int u = __shfl_up_sync(0xffffffffu, s, o);
                    if (lane >= o) s += u;
                }
                if (idx < NB_SCAN) g_boff[idx] = carry + s - v;   // exclusive
                carry += __shfl_sync(0xffffffffu, s, 31);
            }
            __threadfence();
            if (lane == 0) atomicExch(&g_degx[NN + 1], 1);
        }
        if (lane == 0) {
            while (atomicAdd(&g_degx[NN + 1], 0) == 0) { }
            __threadfence();
            block_base = g_boff[blockIdx.x];
        }
    }
    __syncthreads();
    int base = block_base;
    if (i == 0) g_off[0] = 0;
    if (i < NN) {
        int end = base + inc;
        g_off[i + 1] = end;
        g_cursor[i] = end - deg;        // start offset; scatter bumps this
    }

    // grid-wide handoff 2: all cursors visible before scatter
    __syncthreads();
    if (t == 0) {
        __threadfence();
        int t2 = atomicAdd(&g_degx[NN + 2], 1);
        if (t2 == NB_SCAN - 1) atomicExch(&g_degx[NN + 3], 1);
        while (atomicAdd(&g_degx[NN + 3], 0) == 0) { }
        __threadfence();
    }
    __syncthreads();

    // ---- scatter (grid-stride) ----
    int is64 = sh_is64;
    for (int e = blockIdx.x * 1024 + t; e < EETOT; e += NB_SCAN * 1024) {
        int s, d;
        if (e >= EE0) { s = d = e - EE0; }
        else if (is64) { s = ei[2 * e]; d = ei[2 * (EE0 + e)]; }
        else           { s = ei[e];     d = ei[EE0 + e]; }
        int pos = atomicAdd(&g_cursor[d], 1);
        g_esrc[pos] = s;
    }
}

// ---------------- fused agg1: warp per dst node, CSR, no atomics ----------------
__global__ void agg1_kernel(const float* __restrict__ b1) {
    int gid = blockIdx.x * blockDim.x + threadIdx.x;
    int d = gid >> 5;
    int lane = gid & 31;
    if (d >= NN) return;
    int h = lane >> 3;
    const float* __restrict__ als = g_al_src1;
    const int* __restrict__ esrc = g_esrc;
    const __half* __restrict__ h1p = g_h1h;
    float adh = g_al_dst1[d * H1 + h];
    int j0 = g_off[d], j1 = g_off[d + 1];
    float4 acc = make_float4(0.f, 0.f, 0.f, 0.f);
    float den = 0.f;
    int j = j0;
    for (; j + 3 < j1; j += 4) {
        int s0 = esrc[j],     s1 = esrc[j + 1];
        int s2 = esrc[j + 2], s3 = esrc[j + 3];
        float x0 = als[s0 * H1 + h] + adh;
        float x1 = als[s1 * H1 + h] + adh;
        float x2 = als[s2 * H1 + h] + adh;
        float x3 = als[s3 * H1 + h] + adh;
        float a0, a1, a2, a3, c0, c1, c2, c3;
        float e0, e1, e2, e3, f0, f1, f2, f3;
        h4load(&h1p[s0 * HC1 + lane * 4], a0, a1, a2, a3);
        h4load(&h1p[s1 * HC1 + lane * 4], c0, c1, c2, c3);
        h4load(&h1p[s2 * HC1 + lane * 4], e0, e1, e2, e3);
        h4load(&h1p[s3 * HC1 + lane * 4], f0, f1, f2, f3);
        float w0 = wfun(x0), w1 = wfun(x1), w2 = wfun(x2), w3 = wfun(x3);
        den += (w0 + w1) + (w2 + w3);
        acc.x += w0 * a0 + w1 * c0 + w2 * e0 + w3 * f0;
        acc.y += w0 * a1 + w1 * c1 + w2 * e1 + w3 * f1;
        acc.z += w0 * a2 + w1 * c2 + w2 * e2 + w3 * f2;
        acc.w += w0 * a3 + w1 * c3 + w2 * e3 + w3 * f3;
    }
    for (; j < j1; j++) {
        int s0 = esrc[j];
        float x0 = als[s0 * H1 + h] + adh;
        float a0, a1, a2, a3;
        h4load(&h1p[s0 * HC1 + lane * 4], a0, a1, a2, a3);
        float w0 = wfun(x0);
        den += w0;
        acc.x += w0 * a0; acc.y += w0 * a1;
        acc.z += w0 * a2; acc.w += w0 * a3;
    }
    float inv = 1.f / den;      // self-loop guarantees den > 0
    float4 b = *reinterpret_cast<const float4*>(&b1[lane * 4]);
    float4 o;
    o.x = acc.x * inv + b.x; o.y = acc.y * inv + b.y;
    o.z = acc.z * inv + b.z; o.w = acc.w * inv + b.w;
    o.x = o.x > 0.f ? o.x : expm1f(o.x);
    o.y = o.y > 0.f ? o.y : expm1f(o.y);
    o.z = o.z > 0.f ? o.z : expm1f(o.z);
    o.w = o.w > 0.f ? o.w : expm1f(o.w);
    __half2 p0 = __floats2half2_rn(o.x, o.y);
    __half2 p1 = __floats2half2_rn(o.z, o.w);
    uint2 u;
    u.x = *reinterpret_cast<unsigned*>(&p0);
    u.y = *reinterpret_cast<unsigned*>(&p1);
    *reinterpret_cast<uint2*>(&g_out1h[d * HC1 + lane * 4]) = u;
}

// ---------------- GEMM2 + fused logits2 (register-tiled, K-chunked) ----------
// h2[N,32] = out1[N,128] @ W2[128,32]; thread = 4 rows x 4 cols
#define G2_ROWS 128
#define G2_PAD  132
__global__ __launch_bounds__(256) void gemm2_kernel(const float* __restrict__ W2,
                                                    const float* __restrict__ asrc,
                                                    const float* __restrict__ adst) {
    __shared__ float xst[64][G2_PAD];    // ~33 KB  [k][row]
    __shared__ float Wc[64][OUTC];       // 8 KB    [k][col] (current K-chunk)
    int tid = threadIdx.x;
    int row0 = blockIdx.x * G2_ROWS;
    int lane = tid & 31, w = tid >> 5;
    int row_sub = lane >> 3;             // 0..3
    int cg = lane & 7;                   // 0..7
    int rbase = w * 16 + row_sub * 4;    // 4 consecutive rows per thread

    u64 acc2[2][4];                      // [row-pair][col]
#pragma unroll
    for (int m = 0; m < 2; m++)
#pragma unroll
        for (int c = 0; c < 4; c++) acc2[m][c] = 0ull;

#pragma unroll
    for (int kc = 0; kc < 2; kc++) {
        // load W chunk (64x32 floats, contiguous)
        {
            const float4* Wg = (const float4*)(W2 + kc * 64 * OUTC);
            float4* Wc4 = (float4*)Wc;
            Wc4[tid] = Wg[tid];
            Wc4[tid + 256] = Wg[tid + 256];
        }
        // load x chunk transposed: k8-major mapping (conflict-free STS)
#pragma unroll
        for (int i = 0; i < 4; i++) {
            int idx = tid + 256 * i;     // 0..1023
            int k8 = idx >> 7;           // 0..7
            int row = idx & 127;
            int grow = row0 + row;
            uint4 v = make_uint4(0u, 0u, 0u, 0u);
            if (grow < NN) v = *(const uint4*)&g_out1h[grow * HC1 + kc * 64 + k8 * 8];
            const unsigned uu[4] = {v.x, v.y, v.z, v.w};
#pragma unroll
            for (int q = 0; q < 4; q++) {
                __half2 hh = *reinterpret_cast<const __half2*>(&uu[q]);
                float2 ff = __half22float2(hh);
                xst[k8 * 8 + q * 2 + 0][row] = ff.x;
                xst[k8 * 8 + q * 2 + 1][row] = ff.y;
            }
        }
        __syncthreads();

#pragma unroll 16
        for (int k = 0; k < 64; k++) {
            F4U2 xa;
            xa.f4 = *(float4*)&xst[k][rbase];          // 4 rows
            float4 wv = *(float4*)&Wc[k][cg * 4];      // 4 cols
            u64 wd0, wd1, wd2, wd3;
            PACK2(wd0, wv.x, wv.x); PACK2(wd1, wv.y, wv.y);
            PACK2(wd2, wv.z, wv.z); PACK2(wd3, wv.w, wv.w);
#pragma unroll
            for (int m = 0; m < 2; m++) {
                FMA_X2(acc2[m][0], xa.u[m], wd0, acc2[m][0]);
                FMA_X2(acc2[m][1], xa.u[m], wd1, acc2[m][1]);
                FMA_X2(acc2[m][2], xa.u[m], wd2, acc2[m][2]);
                FMA_X2(acc2[m][3], xa.u[m], wd3, acc2[m][3]);
            }
        }
        __syncthreads();
    }

    float acc[4][4];                     // [row][col]
#pragma unroll
    for (int m = 0; m < 2; m++)
#pragma unroll
        for (int c = 0; c < 4; c++)
            UNPACK2(acc[2 * m][c], acc[2 * m + 1][c], acc2[m][c]);

    float4 av = *(const float4*)&asrc[cg * 4];
    float4 bv = *(const float4*)&adst[cg * 4];
#pragma unroll
    for (int r = 0; r < 4; r++) {
        int row = row0 + rbase + r;
        if (row < NN)
            *(float4*)&g_h2f[row * OUTC + cg * 4] = *(float4*)acc[r];
        float ps = acc[r][0] * av.x + acc[r][1] * av.y + acc[r][2] * av.z + acc[r][3] * av.w;
        float pd = acc[r][0] * bv.x + acc[r][1] * bv.y + acc[r][2] * bv.z + acc[r][3] * bv.w;
#pragma unroll
        for (int off = 4; off >= 1; off >>= 1) {
            ps += __shfl_down_sync(0xffffffffu, ps, off);
            pd += __shfl_down_sync(0xffffffffu, pd, off);
        }
        if (cg == 0 && row < NN) {
            g_al_src2[row] = ps * LOG2E;
            g_al_dst2[row] = pd * LOG2E;
        }
    }
}

// ---------------- fused agg2: warp per dst node ----------------
__global__ void agg2_kernel(float* __restrict__ dout, const float* __restrict__ b2) {
    int gid = blockIdx.x * blockDim.x + threadIdx.x;
    int d = gid >> 5;
    int lane = gid & 31;
    if (d >= NN) return;
    const float* __restrict__ als = g_al_src2;
    const int* __restrict__ esrc = g_esrc;
    const float* __restrict__ h2p = g_h2f;
    float ad2 = g_al_dst2[d];
    int j0 = g_off[d], j1 = g_off[d + 1];
    float acc = 0.f, den = 0.f;
    int j = j0;
    for (; j + 3 < j1; j += 4) {
        int s0 = esrc[j],     s1 = esrc[j + 1];
        int s2 = esrc[j + 2], s3 = esrc[j + 3];
        float x0 = als[s0] + ad2, x1 = als[s1] + ad2;
        float x2 = als[s2] + ad2, x3 = als[s3] + ad2;
        float v0 = h2p[s0 * OUTC + lane];
        float v1 = h2p[s1 * OUTC + lane];
        float v2 = h2p[s2 * OUTC + lane];
        float v3 = h2p[s3 * OUTC + lane];
        float w0 = wfun(x0), w1 = wfun(x1), w2 = wfun(x2), w3 = wfun(x3);
        den += (w0 + w1) + (w2 + w3);
        acc += w0 * v0 + w1 * v1 + w2 * v2 + w3 * v3;
    }
    for (; j < j1; j++) {
        int s0 = esrc[j];
        float w0 = wfun(als[s0] + ad2);
        den += w0;
        acc += w0 * h2p[s0 * OUTC + lane];
    }
    dout[d * OUTC + lane] = acc / den + b2[lane];
}

// ---------------- launch ----------------
extern "C" void kernel_launch(void* const* d_in, const int* in_sizes, int n_in,
                              void* d_out, int out_size) {
    const float* x        = (const float*)d_in[0];
    const int*   ei       = (const int*)d_in[1];
    const float* W1       = (const float*)d_in[2];
    const float* att_src1 = (const float*)d_in[3];
    const float* att_dst1 = (const float*)d_in[4];
    const float* b1       = (const float*)d_in[5];
    const float* W2       = (const float*)d_in[6];
    const float* att_src2 = (const float*)d_in[7];
    const float* att_dst2 = (const float*)d_in[8];
    const float* b2       = (const float*)d_in[9];
    float* dout = (float*)d_out;

    const int T = 256;
    void* degx_ptr = nullptr;
    cudaGetSymbolAddress(&degx_ptr, g_degx);
    cudaMemsetAsync(degx_ptr, 0, (NN + 4) * sizeof(int));

    gemm1_kernel<<<(NN + G1_ROWS - 1) / G1_ROWS, 256>>>(x, W1, att_src1, att_dst1, ei);
    scan_kernel<<<NB_SCAN, 1024>>>(ei);
    agg1_kernel<<<(NN * 32 + T - 1) / T, T>>>(b1);

    gemm2_kernel<<<(NN + G2_ROWS - 1) / G2_ROWS, 256>>>(W2, att_src2, att_dst2);
    agg2_kernel<<<(NN * 32 + T - 1) / T, T>>>(dout, b2);
}

// round 10
// speedup vs baseline: 1.2824x; 1.0845x over previous
#include <cuda_runtime.h>
#include <cuda_fp16.h>
#include <math.h>

// ---------------- problem constants ----------------
#define NN   100000
#define EE0  1600000            // raw edges
#define EETOT (EE0 + NN)        // + self loops
#define C1   64                 // in channels
#define H1   4                  // heads layer1
#define HC1  128                // H1*D1
#define OUTC 32                 // layer2 out channels
#define NB_SCAN 98              // ceil(NN/1024)
#define LOG2E 1.4426950408889634f

typedef unsigned long long u64;
#define FMA_X2(d, a, b, c) \
    asm("fma.rn.f32x2 %0, %1, %2, %3;" : "=l"(d) : "l"(a), "l"(b), "l"(c))
#define PACK2(d, lo, hi) \
    asm("mov.b64 %0, {%1, %2};" : "=l"(d) : "f"(lo), "f"(hi))
#define UNPACK2(lo, hi, s) \
    asm("mov.b64 {%0, %1}, %2;" : "=f"(lo), "=f"(hi) : "l"(s))

union F4U2 { float4 f4; u64 u[2]; };

// ---------------- scratch (device globals; no allocation) ----------------
__device__ __half g_h1h[NN * HC1];      // layer1 features (fp16, gather-only)
__device__ __half g_out1h[NN * HC1];    // elu(agg1 + b1) (fp16, gemm2 input)
__device__ float  g_al_src1[NN * H1];   // pre-scaled by log2(e)
__device__ float  g_al_dst1[NN * H1];

__device__ float  g_h2f[NN * OUTC];     // layer2 features (fp32, L2-resident)
__device__ float  g_al_src2[NN];        // pre-scaled by log2(e)
__device__ float  g_al_dst2[NN];

// CSR build: g_degx = [deg[NN], tk0, fl0, tk1, fl1, tk2, fl2] (zeroed by memset)
__device__ int g_degx[NN + 6];
__device__ int g_cursor[NN];
__device__ int g_bsum[NB_SCAN];
__device__ int g_boff[NB_SCAN];
__device__ int g_off[NN + 1];
__device__ int g_esrc[EETOT];

// ---------------- helpers ----------------
__device__ __forceinline__ float ex2(float x) {
    float r;
    asm("ex2.approx.ftz.f32 %0, %1;" : "=f"(r) : "f"(x));
    return r;
}
// weight from pre-scaled logit sum: 2^(leaky(x))
__device__ __forceinline__ float wfun(float x) {
    return ex2(fmaxf(x, 0.2f * x));
}

// int64 little-endian edges => int32 view has zero high words (indices < 2^31)
__device__ __forceinline__ int detect_is64(const int* __restrict__ ei) {
    int zeros = 0;
#pragma unroll
    for (int k = 0; k < 16; k++) zeros += (ei[2 * k + 1] == 0);
    return zeros == 16;
}

__device__ __forceinline__ void h4load(const __half* p, float& f0, float& f1,
                                       float& f2, float& f3) {
    uint2 u = *reinterpret_cast<const uint2*>(p);
    __half2 a = *reinterpret_cast<__half2*>(&u.x);
    __half2 b = *reinterpret_cast<__half2*>(&u.y);
    float2 fa = __half22float2(a), fb = __half22float2(b);
    f0 = fa.x; f1 = fa.y; f2 = fb.x; f3 = fb.y;
}

// grid-wide handoff among NB_SCAN resident blocks (ticket at g_degx[NN+2i],
// flag at g_degx[NN+2i+1]); call from all threads of each block
__device__ __forceinline__ void grid_handoff(int idx) {
    __syncthreads();
    if (threadIdx.x == 0) {
        __threadfence();
        int tk = atomicAdd(&g_degx[NN + 2 * idx], 1);
        if (tk == NB_SCAN - 1) atomicExch(&g_degx[NN + 2 * idx + 1], 1);
        while (atomicAdd(&g_degx[NN + 2 * idx + 1], 0) == 0) { }
        __threadfence();
    }
    __syncthreads();
}

// ---------------- GEMM1 + fused logits1 ----------------
#define G1_ROWS 64
__global__ __launch_bounds__(256) void gemm1_kernel(const float* __restrict__ x,
                                                    const float* __restrict__ W,
                                                    const float* __restrict__ asrc,
                                                    const float* __restrict__ adst) {
    __shared__ float xst[C1][G1_ROWS];   // [k][row] 16 KB
    __shared__ float Ws[C1][HC1];        // 32 KB
    int tid = threadIdx.x;
    int row0 = blockIdx.x * G1_ROWS;

    const float4* W4 = (const float4*)W;
    float4* Ws4 = (float4*)Ws;
#pragma unroll
    for (int i = 0; i < 8; i++) Ws4[tid + 256 * i] = W4[tid + 256 * i];
#pragma unroll
    for (int i = 0; i < 4; i++) {
        int idx = tid + 256 * i;          // float4 idx; 16 per row
        int r = idx >> 4, k4 = idx & 15;
        int row = row0 + r;
        float4 v = make_float4(0.f, 0.f, 0.f, 0.f);
        if (row < NN) v = *(const float4*)&x[row * C1 + k4 * 4];
        xst[k4 * 4 + 0][r] = v.x; xst[k4 * 4 + 1][r] = v.y;
        xst[k4 * 4 + 2][r] = v.z; xst[k4 * 4 + 3][r] = v.w;
    }
    __syncthreads();

    int lane = tid & 31, w = tid >> 5;
    int rb = w * 8;
    u64 acc2[4][4];                     // [row-pair][col]
#pragma unroll
    for (int m = 0; m < 4; m++)
#pragma unroll
        for (int c = 0; c < 4; c++) acc2[m][c] = 0ull;

#pragma unroll
    for (int k = 0; k < C1; k++) {
        F4U2 xa, xb;
        xa.f4 = *(float4*)&xst[k][rb];
        xb.f4 = *(float4*)&xst[k][rb + 4];
        float4 wv = *(float4*)&Ws[k][lane * 4];
        u64 wd[4];
        PACK2(wd[0], wv.x, wv.x); PACK2(wd[1], wv.y, wv.y);
        PACK2(wd[2], wv.z, wv.z); PACK2(wd[3], wv.w, wv.w);
        u64 xp[4] = {xa.u[0], xa.u[1], xb.u[0], xb.u[1]};
#pragma unroll
        for (int m = 0; m < 4; m++) {
            FMA_X2(acc2[m][0], xp[m], wd[0], acc2[m][0]);
            FMA_X2(acc2[m][1], xp[m], wd[1], acc2[m][1]);
            FMA_X2(acc2[m][2], xp[m], wd[2], acc2[m][2]);
            FMA_X2(acc2[m][3], xp[m], wd[3], acc2[m][3]);
        }
    }

    float acc[8][4];
#pragma unroll
    for (int m = 0; m < 4; m++)
#pragma unroll
        for (int c = 0; c < 4; c++)
            UNPACK2(acc[2 * m][c], acc[2 * m + 1][c], acc2[m][c]);

    float4 av = *(const float4*)&asrc[lane * 4];
    float4 bv = *(const float4*)&adst[lane * 4];
    int head = lane >> 3;
#pragma unroll
    for (int r = 0; r < 8; r++) {
        int row = row0 + rb + r;
        if (row < NN) {
            __half2 p0 = __floats2half2_rn(acc[r][0], acc[r][1]);
            __half2 p1 = __floats2half2_rn(acc[r][2], acc[r][3]);
            uint2 u;
            u.x = *reinterpret_cast<unsigned*>(&p0);
            u.y = *reinterpret_cast<unsigned*>(&p1);
            *reinterpret_cast<uint2*>(&g_h1h[row * HC1 + lane * 4]) = u;
        }
        float ps = acc[r][0] * av.x + acc[r][1] * av.y + acc[r][2] * av.z + acc[r][3] * av.w;
        float pd = acc[r][0] * bv.x + acc[r][1] * bv.y + acc[r][2] * bv.z + acc[r][3] * bv.w;
#pragma unroll
        for (int off = 4; off >= 1; off >>= 1) {
            ps += __shfl_down_sync(0xffffffffu, ps, off);
            pd += __shfl_down_sync(0xffffffffu, pd, off);
        }
        if ((lane & 7) == 0 && row < NN) {
            g_al_src1[row * H1 + head] = ps * LOG2E;
            g_al_dst1[row * H1 + head] = pd * LOG2E;
        }
    }
}

// ---------------- hist + scan + scatter: one persistent kernel -------------
// 98 blocks x 1024 threads, all resident => grid handoffs are safe
__global__ __launch_bounds__(1024) void histscan_kernel(const int* __restrict__ ei) {
    __shared__ int warp_tot[32];
    __shared__ int block_base;
    __shared__ int sh_is64;
    int t = threadIdx.x;
    int i = blockIdx.x * 1024 + t;
    int lane = t & 31, w = t >> 5;
    if (t == 0) sh_is64 = detect_is64(ei);
    __syncthreads();
    int is64 = sh_is64;

    // ---- phase 0: dst histogram (grid-stride) ----
    for (int e = blockIdx.x * 1024 + t; e < EETOT; e += NB_SCAN * 1024) {
        int d;
        if (e >= EE0) d = e - EE0;
        else d = is64 ? ei[2 * (EE0 + e)] : ei[EE0 + e];
        atomicAdd(&g_degx[d], 1);
    }
    grid_handoff(0);                    // all histogram atomics visible

    // ---- phase 1: scan ----
    int deg = (i < NN) ? g_degx[i] : 0;
    int sum = deg;
#pragma unroll
    for (int o = 1; o < 32; o <<= 1) {
        int u = __shfl_up_sync(0xffffffffu, sum, o);
        if (lane >= o) sum += u;
    }
    if (lane == 31) warp_tot[w] = sum;
    __syncthreads();
    if (w == 0) {
        int s = warp_tot[lane];
#pragma unroll
        for (int o = 1; o < 32; o <<= 1) {
            int u = __shfl_up_sync(0xffffffffu, s, o);
            if (lane >= o) s += u;
        }
        warp_tot[lane] = s;
    }
    __syncthreads();
    int wbase = (w > 0) ? warp_tot[w - 1] : 0;
    int inc = wbase + sum;              // inclusive scan within block
    if (t == 1023) g_bsum[blockIdx.x] = inc;
    __syncthreads();                    // bsum written before ticket

    if (w == 0) {
        int ticket = 0;
        if (lane == 0) {
            __threadfence();
            ticket = atomicAdd(&g_degx[NN + 2], 1);
        }
        ticket = __shfl_sync(0xffffffffu, ticket, 0);
        if (ticket == NB_SCAN - 1) {
            int carry = 0;
#pragma unroll
            for (int c = 0; c < 4; c++) {
                int idx = c * 32 + lane;
                int v = (idx < NB_SCAN) ? g_bsum[idx] : 0;
                int s = v;
#pragma unroll
                for (int o = 1; o < 32; o <<= 1) {
                    int u = __shfl_up_sync(0xffffffffu, s, o);
                    if (lane >= o) s += u;
                }
                if (idx < NB_SCAN) g_boff[idx] = carry + s - v;   // exclusive
                carry += __shfl_sync(0xffffffffu, s, 31);
            }
            __threadfence();
            if (lane == 0) atomicExch(&g_degx[NN + 3], 1);
        }
        if (lane == 0) {
            while (atomicAdd(&g_degx[NN + 3], 0) == 0) { }
            __threadfence();
            block_base = g_boff[blockIdx.x];
        }
    }
    __syncthreads();
    int base = block_base;
    if (i == 0) g_off[0] = 0;
    if (i < NN) {
        int end = base + inc;
        g_off[i + 1] = end;
        g_cursor[i] = end - deg;        // start offset; scatter bumps this
    }
    grid_handoff(2);                    // all cursors visible before scatter

    // ---- phase 2: scatter (grid-stride) ----
    for (int e = blockIdx.x * 1024 + t; e < EETOT; e += NB_SCAN * 1024) {
        int s, d;
        if (e >= EE0) { s = d = e - EE0; }
        else if (is64) { s = ei[2 * e]; d = ei[2 * (EE0 + e)]; }
        else           { s = ei[e];     d = ei[EE0 + e]; }
        int pos = atomicAdd(&g_cursor[d], 1);
        g_esrc[pos] = s;
    }
}

// ---------------- fused agg1: warp per dst node, CSR, no atomics ----------------
__global__ void agg1_kernel(const float* __restrict__ b1) {
    int gid = blockIdx.x * blockDim.x + threadIdx.x;
    int d = gid >> 5;
    int lane = gid & 31;
    if (d >= NN) return;
    int h = lane >> 3;
    const float* __restrict__ als = g_al_src1;
    const int* __restrict__ esrc = g_esrc;
    const __half* __restrict__ h1p = g_h1h;
    float adh = g_al_dst1[d * H1 + h];
    int j0 = g_off[d], j1 = g_off[d + 1];
    float4 acc = make_float4(0.f, 0.f, 0.f, 0.f);
    float den = 0.f;
    int j = j0;
    for (; j + 3 < j1; j += 4) {
        int s0 = esrc[j],     s1 = esrc[j + 1];
        int s2 = esrc[j + 2], s3 = esrc[j + 3];
        float x0 = als[s0 * H1 + h] + adh;
        float x1 = als[s1 * H1 + h] + adh;
        float x2 = als[s2 * H1 + h] + adh;
        float x3 = als[s3 * H1 + h] + adh;
        float a0, a1, a2, a3, c0, c1, c2, c3;
        float e0, e1, e2, e3, f0, f1, f2, f3;
        h4load(&h1p[s0 * HC1 + lane * 4], a0, a1, a2, a3);
        h4load(&h1p[s1 * HC1 + lane * 4], c0, c1, c2, c3);
        h4load(&h1p[s2 * HC1 + lane * 4], e0, e1, e2, e3);
        h4load(&h1p[s3 * HC1 + lane * 4], f0, f1, f2, f3);
        float w0 = wfun(x0), w1 = wfun(x1), w2 = wfun(x2), w3 = wfun(x3);
        den += (w0 + w1) + (w2 + w3);
        acc.x += w0 * a0 + w1 * c0 + w2 * e0 + w3 * f0;
        acc.y += w0 * a1 + w1 * c1 + w2 * e1 + w3 * f1;
        acc.z += w0 * a2 + w1 * c2 + w2 * e2 + w3 * f2;
        acc.w += w0 * a3 + w1 * c3 + w2 * e3 + w3 * f3;
    }
    for (; j < j1; j++) {
        int s0 = esrc[j];
        float x0 = als[s0 * H1 + h] + adh;
        float a0, a1, a2, a3;
        h4load(&h1p[s0 * HC1 + lane * 4], a0, a1, a2, a3);
        float w0 = wfun(x0);
        den += w0;
        acc.x += w0 * a0; acc.y += w0 * a1;
        acc.z += w0 * a2; acc.w += w0 * a3;
    }
    float inv = 1.f / den;      // self-loop guarantees den > 0
    float4 b = *reinterpret_cast<const float4*>(&b1[lane * 4]);
    float4 o;
    o.x = acc.x * inv + b.x; o.y = acc.y * inv + b.y;
    o.z = acc.z * inv + b.z; o.w = acc.w * inv + b.w;
    o.x = o.x > 0.f ? o.x : expm1f(o.x);
    o.y = o.y > 0.f ? o.y : expm1f(o.y);
    o.z = o.z > 0.f ? o.z : expm1f(o.z);
    o.w = o.w > 0.f ? o.w : expm1f(o.w);
    __half2 p0 = __floats2half2_rn(o.x, o.y);
    __half2 p1 = __floats2half2_rn(o.z, o.w);
    uint2 u;
    u.x = *reinterpret_cast<unsigned*>(&p0);
    u.y = *reinterpret_cast<unsigned*>(&p1);
    *reinterpret_cast<uint2*>(&g_out1h[d * HC1 + lane * 4]) = u;
}

// ---------------- GEMM2 + fused logits2 (register-tiled, K-chunked) ----------
#define G2_ROWS 128
#define G2_PAD  132
__global__ __launch_bounds__(256) void gemm2_kernel(const float* __restrict__ W2,
                                                    const float* __restrict__ asrc,
                                                    const float* __restrict__ adst) {
    __shared__ float xst[64][G2_PAD];    // ~33 KB  [k][row]
    __shared__ float Wc[64][OUTC];       // 8 KB    [k][col] (current K-chunk)
    int tid = threadIdx.x;
    int row0 = blockIdx.x * G2_ROWS;
    int lane = tid & 31, w = tid >> 5;
    int row_sub = lane >> 3;             // 0..3
    int cg = lane & 7;                   // 0..7
    int rbase = w * 16 + row_sub * 4;    // 4 consecutive rows per thread

    u64 acc2[2][4];                      // [row-pair][col]
#pragma unroll
    for (int m = 0; m < 2; m++)
#pragma unroll
        for (int c = 0; c < 4; c++) acc2[m][c] = 0ull;

#pragma unroll
    for (int kc = 0; kc < 2; kc++) {
        {
            const float4* Wg = (const float4*)(W2 + kc * 64 * OUTC);
            float4* Wc4 = (float4*)Wc;
            Wc4[tid] = Wg[tid];
            Wc4[tid + 256] = Wg[tid + 256];
        }
#pragma unroll
        for (int i = 0; i < 4; i++) {
            int idx = tid + 256 * i;     // 0..1023
            int k8 = idx >> 7;           // 0..7
            int row = idx & 127;
            int grow = row0 + row;
            uint4 v = make_uint4(0u, 0u, 0u, 0u);
            if (grow < NN) v = *(const uint4*)&g_out1h[grow * HC1 + kc * 64 + k8 * 8];
            const unsigned uu[4] = {v.x, v.y, v.z, v.w};
#pragma unroll
            for (int q = 0; q < 4; q++) {
                __half2 hh = *reinterpret_cast<const __half2*>(&uu[q]);
                float2 ff = __half22float2(hh);
                xst[k8 * 8 + q * 2 + 0][row] = ff.x;
                xst[k8 * 8 + q * 2 + 1][row] = ff.y;
            }
        }
        __syncthreads();

#pragma unroll 16
        for (int k = 0; k < 64; k++) {
            F4U2 xa;
            xa.f4 = *(float4*)&xst[k][rbase];          // 4 rows
            float4 wv = *(float4*)&Wc[k][cg * 4];      // 4 cols
            u64 wd0, wd1, wd2, wd3;
            PACK2(wd0, wv.x, wv.x); PACK2(wd1, wv.y, wv.y);
            PACK2(wd2, wv.z, wv.z); PACK2(wd3, wv.w, wv.w);
#pragma unroll
            for (int m = 0; m < 2; m++) {
                FMA_X2(acc2[m][0], xa.u[m], wd0, acc2[m][0]);
                FMA_X2(acc2[m][1], xa.u[m], wd1, acc2[m][1]);
                FMA_X2(acc2[m][2], xa.u[m], wd2, acc2[m][2]);
                FMA_X2(acc2[m][3], xa.u[m], wd3, acc2[m][3]);
            }
        }
        __syncthreads();
    }

    float acc[4][4];                     // [row][col]
#pragma unroll
    for (int m = 0; m < 2; m++)
#pragma unroll
        for (int c = 0; c < 4; c++)
            UNPACK2(acc[2 * m][c], acc[2 * m + 1][c], acc2[m][c]);

    float4 av = *(const float4*)&asrc[cg * 4];
    float4 bv = *(const float4*)&adst[cg * 4];
#pragma unroll
    for (int r = 0; r < 4; r++) {
        int row = row0 + rbase + r;
        if (row < NN)
            *(float4*)&g_h2f[row * OUTC + cg * 4] = *(float4*)acc[r];
        float ps = acc[r][0] * av.x + acc[r][1] * av.y + acc[r][2] * av.z + acc[r][3] * av.w;
        float pd = acc[r][0] * bv.x + acc[r][1] * bv.y + acc[r][2] * bv.z + acc[r][3] * bv.w;
#pragma unroll
        for (int off = 4; off >= 1; off >>= 1) {
            ps += __shfl_down_sync(0xffffffffu, ps, off);
            pd += __shfl_down_sync(0xffffffffu, pd, off);
        }
        if (cg == 0 && row < NN) {
            g_al_src2[row] = ps * LOG2E;
            g_al_dst2[row] = pd * LOG2E;
        }
    }
}

// ---------------- fused agg2: warp per dst node ----------------
__global__ void agg2_kernel(float* __restrict__ dout, const float* __restrict__ b2) {
    int gid = blockIdx.x * blockDim.x + threadIdx.x;
    int d = gid >> 5;
    int lane = gid & 31;
    if (d >= NN) return;
    const float* __restrict__ als = g_al_src2;
    const int* __restrict__ esrc = g_esrc;
    const float* __restrict__ h2p = g_h2f;
    float ad2 = g_al_dst2[d];
    int j0 = g_off[d], j1 = g_off[d + 1];
    float acc = 0.f, den = 0.f;
    int j = j0;
    for (; j + 3 < j1; j += 4) {
        int s0 = esrc[j],     s1 = esrc[j + 1];
        int s2 = esrc[j + 2], s3 = esrc[j + 3];
        float x0 = als[s0] + ad2, x1 = als[s1] + ad2;
        float x2 = als[s2] + ad2, x3 = als[s3] + ad2;
        float v0 = h2p[s0 * OUTC + lane];
        float v1 = h2p[s1 * OUTC + lane];
        float v2 = h2p[s2 * OUTC + lane];
        float v3 = h2p[s3 * OUTC + lane];
        float w0 = wfun(x0), w1 = wfun(x1), w2 = wfun(x2), w3 = wfun(x3);
        den += (w0 + w1) + (w2 + w3);
        acc += w0 * v0 + w1 * v1 + w2 * v2 + w3 * v3;
    }
    for (; j < j1; j++) {
        int s0 = esrc[j];
        float w0 = wfun(als[s0] + ad2);
        den += w0;
        acc += w0 * h2p[s0 * OUTC + lane];
    }
    dout[d * OUTC + lane] = acc / den + b2[lane];
}

// ---------------- launch ----------------
extern "C" void kernel_launch(void* const* d_in, const int* in_sizes, int n_in,
                              void* d_out, int out_size) {
    const float* x        = (const float*)d_in[0];
    const int*   ei       = (const int*)d_in[1];
    const float* W1       = (const float*)d_in[2];
    const float* att_src1 = (const float*)d_in[3];
    const float* att_dst1 = (const float*)d_in[4];
    const float* b1       = (const float*)d_in[5];
    const float* W2       = (const float*)d_in[6];
    const float* att_src2 = (const float*)d_in[7];
    const float* att_dst2 = (const float*)d_in[8];
    const float* b2       = (const float*)d_in[9];
    float* dout = (float*)d_out;

    const int T = 256;
    void* degx_ptr = nullptr;
    cudaGetSymbolAddress(&degx_ptr, g_degx);

    // fork: CSR build (memory/atomic-bound) runs concurrently with gemm1
    // (FFMA-bound). Streams/events are host-side objects only (no device
    // allocation); intentionally not destroyed — kernel_launch runs O(1) times.
    cudaStream_t s2;
    cudaStreamCreate(&s2);
    cudaEvent_t eFork, eJoin;
    cudaEventCreateWithFlags(&eFork, cudaEventDisableTiming);
    cudaEventCreateWithFlags(&eJoin, cudaEventDisableTiming);

    cudaEventRecord(eFork, 0);
    cudaStreamWaitEvent(s2, eFork, 0);
    cudaMemsetAsync(degx_ptr, 0, (NN + 6) * sizeof(int), s2);
    histscan_kernel<<<NB_SCAN, 1024, 0, s2>>>(ei);
    cudaEventRecord(eJoin, s2);

    gemm1_kernel<<<(NN + G1_ROWS - 1) / G1_ROWS, 256>>>(x, W1, att_src1, att_dst1);

    cudaStreamWaitEvent(0, eJoin, 0);
    agg1_kernel<<<(NN * 32 + T - 1) / T, T>>>(b1);

    gemm2_kernel<<<(NN + G2_ROWS - 1) / G2_ROWS, 256>>>(W2, att_src2, att_dst2);
    agg2_kernel<<<(NN * 32 + T - 1) / T, T>>>(dout, b2);
}